// round 2
// baseline (speedup 1.0000x reference)
#include <cuda_runtime.h>
#include <cstdint>

// Problem constants (asserted by reference):
//   x: [8, 128, 128, 128]  (B, D, H, W), HW = 16384, NPIX = 131072
//   C = 128 classes, M = 1, NEG = 3  -> 512 prototypes total
// Output tuple flattened in order:
//   cls_score  [8,128,128,128]      @ 0          (16777216)
//   distances  [8,128,1,128,128]    @ 16777216   (16777216)
//   distances_neg [8,128,3,128,128] @ 33554432   (50331648)
//   probs_ori  [8,128,128,128]      @ 83886080   (16777216)

typedef unsigned long long ull;

// Prototype matrix, pre-transposed per 128-proto chunk: g_PT[chunk*16384 + d*128 + cLocal]
// chunk 0..2 = negative prototypes n=0..2 (per class), chunk 3 = positive prototypes.
__device__ float g_PT[4 * 128 * 128];

// ---------------------------------------------------------------------------
// Prep: normalize reps, build negative prototypes, store transposed.
// grid = 128 (one CTA per class), block = 128 (one thread per channel d)
// ---------------------------------------------------------------------------
__global__ void dml_prep(const float* __restrict__ reps_w,
                         const float* __restrict__ fc_w,
                         const float* __restrict__ fc_b) {
    __shared__ float repn[128];
    __shared__ float red[128];
    const int c = blockIdx.x;
    const int d = threadIdx.x;

    float w = reps_w[c * 128 + d];
    red[d] = w * w;
    __syncthreads();
    for (int s = 64; s > 0; s >>= 1) { if (d < s) red[d] += red[d + s]; __syncthreads(); }
    float S = red[0];
    __syncthreads();
    float rn = w / fmaxf(sqrtf(S), 1e-12f);
    repn[d] = rn;
    g_PT[3 * 16384 + d * 128 + c] = rn;   // positive prototypes, chunk 3
    __syncthreads();

    for (int n = 0; n < 3; n++) {
        const float* wr = fc_w + (size_t)(n * 128 + d) * 128;
        float a = fc_b[n * 128 + d];
        #pragma unroll 8
        for (int k = 0; k < 128; k++) a += repn[k] * wr[k];
        float v = a + rn;                 // neg_off + reps_flat
        red[d] = v * v;
        __syncthreads();
        for (int s = 64; s > 0; s >>= 1) { if (d < s) red[d] += red[d + s]; __syncthreads(); }
        float S2 = red[0];
        __syncthreads();
        g_PT[n * 16384 + d * 128 + c] = v / fmaxf(sqrtf(S2), 1e-12f);
    }
}

// ---------------------------------------------------------------------------
// Packed fp32x2 helpers (Blackwell FFMA2 — only reachable via PTX)
// ---------------------------------------------------------------------------
__device__ __forceinline__ ull pk(float v) {
    ull r; asm("mov.b64 %0, {%1,%1};" : "=l"(r) : "f"(v)); return r;
}
__device__ __forceinline__ void fma2(ull& d, ull a, ull b) {
    asm("fma.rn.f32x2 %0, %1, %2, %0;" : "+l"(d) : "l"(a), "l"(b));
}
__device__ __forceinline__ void unpk(ull v, float& lo, float& hi) {
    asm("mov.b64 {%0,%1}, %2;" : "=f"(lo), "=f"(hi) : "l"(v));
}
union F4U { float4 f; ull u[2]; };

// ---------------------------------------------------------------------------
// Main fused kernel.
// grid = 2048 (8 batches * 256 pixel-tiles), block = 128 threads.
// Each CTA: 64 contiguous hw pixels of one batch image.
// Thread tile: 8 px * 8 protos (protos packed pairwise for f32x2).
// smem: xs[128k][64px] | pt[128k][128proto] | dbuf[128c][64px] | mn[128c][64px]
//       | rs[64] | part[128]   (total 41152 floats = 164608 B)
// ---------------------------------------------------------------------------
__global__ __launch_bounds__(128, 1)
void dml_main(const float* __restrict__ x, float* __restrict__ out) {
    extern __shared__ float sm[];
    float* xs   = sm;            // 8192
    float* pt   = sm + 8192;     // 16384
    float* dbuf = sm + 24576;    // 8192
    float* mn   = sm + 32768;    // 8192
    float* rs   = sm + 40960;    // 64
    float* part = sm + 41024;    // 128

    const int tid = threadIdx.x;
    const int b   = blockIdx.x >> 8;
    const int hw0 = (blockIdx.x & 255) << 6;
    const float* xb = x + ((size_t)b * 128) * 16384 + hw0;

    // Load x tile: xs[d][px] — contiguous px dimension, coalesced.
    for (int i = tid; i < 8192; i += 128)
        xs[i] = xb[(size_t)(i >> 6) * 16384 + (i & 63)];
    __syncthreads();

    // Per-pixel L2 norm, fold into xs (emb = x / max(||x||, eps)).
    {
        int p = tid & 63, h = tid >> 6;
        float s = 0.f;
        #pragma unroll 8
        for (int d = 0; d < 64; d++) { float v = xs[(h * 64 + d) * 64 + p]; s += v * v; }
        part[tid] = s;
    }
    __syncthreads();
    if (tid < 64) rs[tid] = 1.0f / fmaxf(sqrtf(part[tid] + part[tid + 64]), 1e-12f);
    __syncthreads();
    for (int i = tid; i < 8192; i += 128) xs[i] *= rs[i & 63];

    const int tx = tid & 7;    // pixel-group  (8 px each)
    const int ty = tid >> 3;   // proto-group  (8 protos each)
    const float4* xs4 = (const float4*)xs;
    const float4* pt4 = (const float4*)pt;

    for (int cc = 0; cc < 4; cc++) {
        __syncthreads();   // protect pt + dbuf reuse
        {
            const float4* gp = (const float4*)(g_PT + cc * 16384);
            float4* w4 = (float4*)pt;
            for (int i = tid; i < 4096; i += 128) w4[i] = gp[i];
        }
        __syncthreads();

        ull acc[8][4];
        #pragma unroll
        for (int i = 0; i < 8; i++)
            #pragma unroll
            for (int j = 0; j < 4; j++) acc[i][j] = 0ULL;

        #pragma unroll 4
        for (int k = 0; k < 128; k++) {
            float4 xa = xs4[k * 16 + tx * 2];
            float4 xc = xs4[k * 16 + tx * 2 + 1];
            F4U p0, p1;
            p0.f = pt4[k * 32 + ty * 2];
            p1.f = pt4[k * 32 + ty * 2 + 1];
            ull xq[8] = { pk(xa.x), pk(xa.y), pk(xa.z), pk(xa.w),
                          pk(xc.x), pk(xc.y), pk(xc.z), pk(xc.w) };
            #pragma unroll
            for (int i = 0; i < 8; i++) {
                fma2(acc[i][0], p0.u[0], xq[i]);
                fma2(acc[i][1], p0.u[1], xq[i]);
                fma2(acc[i][2], p1.u[0], xq[i]);
                fma2(acc[i][3], p1.u[1], xq[i]);
            }
        }

        if (cc < 3) {
            // Negative chunk: distances_neg + running min.
            #pragma unroll
            for (int i = 0; i < 8; i++) {
                int p = tx * 8 + i;
                #pragma unroll
                for (int j = 0; j < 4; j++) {
                    float lo, hi; unpk(acc[i][j], lo, hi);
                    int c0 = ty * 8 + 2 * j;
                    float da = sqrtf(fmaxf(2.f - 2.f * lo, 1e-12f));
                    float db = sqrtf(fmaxf(2.f - 2.f * hi, 1e-12f));
                    dbuf[c0 * 64 + p] = da;
                    dbuf[(c0 + 1) * 64 + p] = db;
                    if (cc == 0) {
                        mn[c0 * 64 + p] = da;
                        mn[(c0 + 1) * 64 + p] = db;
                    } else {
                        mn[c0 * 64 + p] = fminf(mn[c0 * 64 + p], da);
                        mn[(c0 + 1) * 64 + p] = fminf(mn[(c0 + 1) * 64 + p], db);
                    }
                }
            }
            __syncthreads();
            // Coalesced float4 writes of distances_neg for n = cc.
            const float4* d4 = (const float4*)dbuf;
            #pragma unroll
            for (int it = 0; it < 16; it++) {
                int e = it * 128 + tid;
                int c = e >> 4;
                int q = (e & 15) << 2;
                float4 v = d4[e];
                *(float4*)(out + 33554432u
                           + (size_t)((b * 128 + c) * 3 + cc) * 16384 + hw0 + q) = v;
            }
        } else {
            // Positive chunk: dist, probs, probs_ori, cls normalization.
            #pragma unroll
            for (int i = 0; i < 8; i++) {
                int p = tx * 8 + i;
                #pragma unroll
                for (int j = 0; j < 4; j++) {
                    float lo, hi; unpk(acc[i][j], lo, hi);
                    int c0 = ty * 8 + 2 * j;
                    float dots[2] = { lo, hi };
                    #pragma unroll
                    for (int h2 = 0; h2 < 2; h2++) {
                        int ci = c0 + h2;
                        float m    = fmaxf(2.f - 2.f * dots[h2], 1e-12f);
                        float dist = sqrtf(m);
                        float mv   = mn[ci * 64 + p];
                        float t    = dist + 0.3f * (2.f - mv);
                        float pr   = __expf(-2.f * t * t);
                        dbuf[ci * 64 + p] = dist;   // distances
                        mn[ci * 64 + p]   = pr;     // probs (reuse buffer)
                    }
                }
            }
            __syncthreads();
            // Per-pixel sum of probs over classes.
            {
                int p = tid & 63, h = tid >> 6;
                float s = 0.f;
                #pragma unroll 8
                for (int c = 0; c < 64; c++) s += mn[(h * 64 + c) * 64 + p];
                part[tid] = s;
            }
            __syncthreads();
            if (tid < 64) rs[tid] = 1.0f / (part[tid] + part[tid + 64]);
            __syncthreads();
            // Coalesced float4 writes: cls_score, distances, probs_ori.
            const float4* d4 = (const float4*)dbuf;
            const float4* p4 = (const float4*)mn;
            const float4* r4 = (const float4*)rs;
            #pragma unroll
            for (int it = 0; it < 16; it++) {
                int e = it * 128 + tid;
                int c = e >> 4;
                int q = (e & 15) << 2;
                float4 dv = d4[e], pv = p4[e], rv = r4[e & 15];
                float4 ev, po, cs;
                ev.x = __expf(-dv.x * dv.x); ev.y = __expf(-dv.y * dv.y);
                ev.z = __expf(-dv.z * dv.z); ev.w = __expf(-dv.w * dv.w);
                po.x = ev.x * ev.x; po.y = ev.y * ev.y;
                po.z = ev.z * ev.z; po.w = ev.w * ev.w;
                cs.x = ev.x * pv.x * rv.x; cs.y = ev.y * pv.y * rv.y;
                cs.z = ev.z * pv.z * rv.z; cs.w = ev.w * pv.w * rv.w;
                size_t base = (size_t)(b * 128 + c) * 16384 + hw0 + q;
                *(float4*)(out + base)             = cs;  // cls_score
                *(float4*)(out + 16777216u + base) = dv;  // distances
                *(float4*)(out + 83886080u + base) = po;  // probs_ori
            }
        }
    }
}

// ---------------------------------------------------------------------------
extern "C" void kernel_launch(void* const* d_in, const int* in_sizes, int n_in,
                              void* d_out, int out_size) {
    const float* x    = (const float*)d_in[0];
    const float* reps = (const float*)d_in[1];
    const float* fcw  = (const float*)d_in[2];
    const float* fcb  = (const float*)d_in[3];
    float* out = (float*)d_out;

    const int smem = 41152 * (int)sizeof(float);   // 164608 B
    cudaFuncSetAttribute(dml_main, cudaFuncAttributeMaxDynamicSharedMemorySize, smem);

    dml_prep<<<128, 128>>>(reps, fcw, fcb);
    dml_main<<<2048, 128, smem>>>(x, out);
}

// round 3
// speedup vs baseline: 1.0021x; 1.0021x over previous
#include <cuda_runtime.h>
#include <cstdint>

// Problem constants (asserted by reference):
//   x: [8, 128, 128, 128]  (B, D, H, W), HW = 16384, NPIX = 131072
//   C = 128 classes, M = 1, NEG = 3  -> 512 prototypes total
// Output tuple flattened in order:
//   cls_score  [8,128,128,128]      @ 0          (16777216)
//   distances  [8,128,1,128,128]    @ 16777216   (16777216)
//   distances_neg [8,128,3,128,128] @ 33554432   (50331648)
//   probs_ori  [8,128,128,128]      @ 83886080   (16777216)

typedef unsigned long long ull;

// Prototype matrix, pre-transposed per 128-proto chunk: g_PT[chunk*16384 + d*128 + cLocal]
// chunk 0..2 = negative prototypes n=0..2 (per class), chunk 3 = positive prototypes.
__device__ float g_PT[4 * 128 * 128];

// ---------------------------------------------------------------------------
// Prep: normalize reps, build negative prototypes, store transposed.
// grid = 128 (one CTA per class), block = 128 (one thread per channel d)
// ---------------------------------------------------------------------------
__global__ void dml_prep(const float* __restrict__ reps_w,
                         const float* __restrict__ fc_w,
                         const float* __restrict__ fc_b) {
    __shared__ float repn[128];
    __shared__ float red[128];
    const int c = blockIdx.x;
    const int d = threadIdx.x;

    float w = reps_w[c * 128 + d];
    red[d] = w * w;
    __syncthreads();
    for (int s = 64; s > 0; s >>= 1) { if (d < s) red[d] += red[d + s]; __syncthreads(); }
    float S = red[0];
    __syncthreads();
    float rn = w / fmaxf(sqrtf(S), 1e-12f);
    repn[d] = rn;
    g_PT[3 * 16384 + d * 128 + c] = rn;   // positive prototypes, chunk 3
    __syncthreads();

    for (int n = 0; n < 3; n++) {
        const float* wr = fc_w + (size_t)(n * 128 + d) * 128;
        float a = fc_b[n * 128 + d];
        #pragma unroll 8
        for (int k = 0; k < 128; k++) a += repn[k] * wr[k];
        float v = a + rn;                 // neg_off + reps_flat
        red[d] = v * v;
        __syncthreads();
        for (int s = 64; s > 0; s >>= 1) { if (d < s) red[d] += red[d + s]; __syncthreads(); }
        float S2 = red[0];
        __syncthreads();
        g_PT[n * 16384 + d * 128 + c] = v / fmaxf(sqrtf(S2), 1e-12f);
    }
}

// ---------------------------------------------------------------------------
// Packed fp32x2 helpers (Blackwell FFMA2 — only reachable via PTX)
// ---------------------------------------------------------------------------
__device__ __forceinline__ ull pk(float v) {
    ull r; asm("mov.b64 %0, {%1,%1};" : "=l"(r) : "f"(v)); return r;
}
__device__ __forceinline__ void fma2(ull& d, ull a, ull b) {
    asm("fma.rn.f32x2 %0, %1, %2, %0;" : "+l"(d) : "l"(a), "l"(b));
}
__device__ __forceinline__ void unpk(ull v, float& lo, float& hi) {
    asm("mov.b64 {%0,%1}, %2;" : "=f"(lo), "=f"(hi) : "l"(v));
}
union F4U { float4 f; ull u[2]; };

// ---------------------------------------------------------------------------
// Main fused kernel.
// grid = 2048 (8 batches * 256 pixel-tiles), block = 128 threads.
// Each CTA: 64 contiguous hw pixels of one batch image.
// Thread tile: 8 px * 8 protos (protos packed pairwise for f32x2).
// smem: xs[128k][64px] | pt[128k][128proto] | dbuf[128c][64px] | mn[128c][64px]
//       | rs[64] | part[128]   (total 41152 floats = 164608 B)
// ---------------------------------------------------------------------------
__global__ __launch_bounds__(128, 1)
void dml_main(const float* __restrict__ x, float* __restrict__ out) {
    extern __shared__ float sm[];
    float* xs   = sm;            // 8192
    float* pt   = sm + 8192;     // 16384
    float* dbuf = sm + 24576;    // 8192
    float* mn   = sm + 32768;    // 8192
    float* rs   = sm + 40960;    // 64
    float* part = sm + 41024;    // 128

    const int tid = threadIdx.x;
    const int b   = blockIdx.x >> 8;
    const int hw0 = (blockIdx.x & 255) << 6;
    const float* xb = x + ((size_t)b * 128) * 16384 + hw0;

    // Load x tile: xs[d][px] — contiguous px dimension, coalesced.
    for (int i = tid; i < 8192; i += 128)
        xs[i] = xb[(size_t)(i >> 6) * 16384 + (i & 63)];
    __syncthreads();

    // Per-pixel L2 norm, fold into xs (emb = x / max(||x||, eps)).
    {
        int p = tid & 63, h = tid >> 6;
        float s = 0.f;
        #pragma unroll 8
        for (int d = 0; d < 64; d++) { float v = xs[(h * 64 + d) * 64 + p]; s += v * v; }
        part[tid] = s;
    }
    __syncthreads();
    if (tid < 64) rs[tid] = 1.0f / fmaxf(sqrtf(part[tid] + part[tid + 64]), 1e-12f);
    __syncthreads();
    for (int i = tid; i < 8192; i += 128) xs[i] *= rs[i & 63];

    const int tx = tid & 7;    // pixel-group  (8 px each)
    const int ty = tid >> 3;   // proto-group  (8 protos each)
    const float4* xs4 = (const float4*)xs;
    const float4* pt4 = (const float4*)pt;

    for (int cc = 0; cc < 4; cc++) {
        __syncthreads();   // protect pt + dbuf reuse
        {
            const float4* gp = (const float4*)(g_PT + cc * 16384);
            float4* w4 = (float4*)pt;
            for (int i = tid; i < 4096; i += 128) w4[i] = gp[i];
        }
        __syncthreads();

        ull acc[8][4];
        #pragma unroll
        for (int i = 0; i < 8; i++)
            #pragma unroll
            for (int j = 0; j < 4; j++) acc[i][j] = 0ULL;

        #pragma unroll 4
        for (int k = 0; k < 128; k++) {
            float4 xa = xs4[k * 16 + tx * 2];
            float4 xc = xs4[k * 16 + tx * 2 + 1];
            F4U p0, p1;
            p0.f = pt4[k * 32 + ty * 2];
            p1.f = pt4[k * 32 + ty * 2 + 1];
            ull xq[8] = { pk(xa.x), pk(xa.y), pk(xa.z), pk(xa.w),
                          pk(xc.x), pk(xc.y), pk(xc.z), pk(xc.w) };
            #pragma unroll
            for (int i = 0; i < 8; i++) {
                fma2(acc[i][0], p0.u[0], xq[i]);
                fma2(acc[i][1], p0.u[1], xq[i]);
                fma2(acc[i][2], p1.u[0], xq[i]);
                fma2(acc[i][3], p1.u[1], xq[i]);
            }
        }

        if (cc < 3) {
            // Negative chunk: distances_neg + running min.
            #pragma unroll
            for (int i = 0; i < 8; i++) {
                int p = tx * 8 + i;
                #pragma unroll
                for (int j = 0; j < 4; j++) {
                    float lo, hi; unpk(acc[i][j], lo, hi);
                    int c0 = ty * 8 + 2 * j;
                    float da = sqrtf(fmaxf(2.f - 2.f * lo, 1e-12f));
                    float db = sqrtf(fmaxf(2.f - 2.f * hi, 1e-12f));
                    dbuf[c0 * 64 + p] = da;
                    dbuf[(c0 + 1) * 64 + p] = db;
                    if (cc == 0) {
                        mn[c0 * 64 + p] = da;
                        mn[(c0 + 1) * 64 + p] = db;
                    } else {
                        mn[c0 * 64 + p] = fminf(mn[c0 * 64 + p], da);
                        mn[(c0 + 1) * 64 + p] = fminf(mn[(c0 + 1) * 64 + p], db);
                    }
                }
            }
            __syncthreads();
            // Coalesced float4 writes of distances_neg for n = cc.
            const float4* d4 = (const float4*)dbuf;
            #pragma unroll
            for (int it = 0; it < 16; it++) {
                int e = it * 128 + tid;
                int c = e >> 4;
                int q = (e & 15) << 2;
                float4 v = d4[e];
                *(float4*)(out + 33554432u
                           + (size_t)((b * 128 + c) * 3 + cc) * 16384 + hw0 + q) = v;
            }
        } else {
            // Positive chunk: dist, probs, probs_ori, cls normalization.
            #pragma unroll
            for (int i = 0; i < 8; i++) {
                int p = tx * 8 + i;
                #pragma unroll
                for (int j = 0; j < 4; j++) {
                    float lo, hi; unpk(acc[i][j], lo, hi);
                    int c0 = ty * 8 + 2 * j;
                    float dots[2] = { lo, hi };
                    #pragma unroll
                    for (int h2 = 0; h2 < 2; h2++) {
                        int ci = c0 + h2;
                        float m    = fmaxf(2.f - 2.f * dots[h2], 1e-12f);
                        float dist = sqrtf(m);
                        float mv   = mn[ci * 64 + p];
                        float t    = dist + 0.3f * (2.f - mv);
                        float pr   = __expf(-2.f * t * t);
                        dbuf[ci * 64 + p] = dist;   // distances
                        mn[ci * 64 + p]   = pr;     // probs (reuse buffer)
                    }
                }
            }
            __syncthreads();
            // Per-pixel sum of probs over classes.
            {
                int p = tid & 63, h = tid >> 6;
                float s = 0.f;
                #pragma unroll 8
                for (int c = 0; c < 64; c++) s += mn[(h * 64 + c) * 64 + p];
                part[tid] = s;
            }
            __syncthreads();
            if (tid < 64) rs[tid] = 1.0f / (part[tid] + part[tid + 64]);
            __syncthreads();
            // Coalesced float4 writes: cls_score, distances, probs_ori.
            const float4* d4 = (const float4*)dbuf;
            const float4* p4 = (const float4*)mn;
            const float4* r4 = (const float4*)rs;
            #pragma unroll
            for (int it = 0; it < 16; it++) {
                int e = it * 128 + tid;
                int c = e >> 4;
                int q = (e & 15) << 2;
                float4 dv = d4[e], pv = p4[e], rv = r4[e & 15];
                float4 ev, po, cs;
                ev.x = __expf(-dv.x * dv.x); ev.y = __expf(-dv.y * dv.y);
                ev.z = __expf(-dv.z * dv.z); ev.w = __expf(-dv.w * dv.w);
                po.x = ev.x * ev.x; po.y = ev.y * ev.y;
                po.z = ev.z * ev.z; po.w = ev.w * ev.w;
                cs.x = ev.x * pv.x * rv.x; cs.y = ev.y * pv.y * rv.y;
                cs.z = ev.z * pv.z * rv.z; cs.w = ev.w * pv.w * rv.w;
                size_t base = (size_t)(b * 128 + c) * 16384 + hw0 + q;
                *(float4*)(out + base)             = cs;  // cls_score
                *(float4*)(out + 16777216u + base) = dv;  // distances
                *(float4*)(out + 83886080u + base) = po;  // probs_ori
            }
        }
    }
}

// ---------------------------------------------------------------------------
extern "C" void kernel_launch(void* const* d_in, const int* in_sizes, int n_in,
                              void* d_out, int out_size) {
    const float* x    = (const float*)d_in[0];
    const float* reps = (const float*)d_in[1];
    const float* fcw  = (const float*)d_in[2];
    const float* fcb  = (const float*)d_in[3];
    float* out = (float*)d_out;

    const int smem = 41152 * (int)sizeof(float);   // 164608 B
    cudaFuncSetAttribute(dml_main, cudaFuncAttributeMaxDynamicSharedMemorySize, smem);

    dml_prep<<<128, 128>>>(reps, fcw, fcb);
    dml_main<<<2048, 128, smem>>>(x, out);
}